// round 5
// baseline (speedup 1.0000x reference)
#include <cuda_runtime.h>

// Problem constants (fixed by the dataset): B=512, T=512, L=128
#define BB 512
#define TT 512
#define LL 128
#define NB 4                 // batches per CTA
#define NCTA (BB / NB)       // 128 CTAs -> one wave on 148 SMs
#define NTHR 256             // 2 warp-groups; wg splits the i-dimension
#define GROWTH 4.8520303f    // ln(128): expected per-step growth of log-partition

__device__ __forceinline__ unsigned long long pack2(float x, float y) {
    unsigned long long r;
    asm("mov.b64 %0, {%1, %2};" : "=l"(r) : "f"(x), "f"(y));
    return r;
}
__device__ __forceinline__ void unpack2(float& x, float& y, unsigned long long v) {
    asm("mov.b64 {%0, %1}, %2;" : "=f"(x), "=f"(y) : "l"(v));
}
// Packed f32x2 FMA — 2x fp32 throughput on sm_103a.
__device__ __forceinline__ unsigned long long fma2(unsigned long long a,
                                                   unsigned long long b,
                                                   unsigned long long c) {
    unsigned long long d;
    asm("fma.rn.f32x2 %0, %1, %2, %3;" : "=l"(d) : "l"(a), "l"(b), "l"(c));
    return d;
}
__device__ __forceinline__ unsigned long long add2(unsigned long long a,
                                                   unsigned long long b) {
    unsigned long long d;
    asm("add.rn.f32x2 %0, %1, %2;" : "=l"(d) : "l"(a), "l"(b));
    return d;
}

// Persistent: one CTA = NB=4 batches for the whole scan. 256 threads.
//   j  = tid & 127  : output label owned by this thread (both warp-groups)
//   wg = tid >> 7   : i-half  [64*wg, 64*wg+64)
// E[i-half, j] in registers (32 f32x2). Each SMSP hosts one warp from each
// warp-group -> 2 independent instruction streams hide LDS/MUFU latency.
// wg1 does only the FMA partials; wg0 owns the serial log/exp recurrence.
__global__ __launch_bounds__(NTHR, 1) void crf_kernel(
    const float* __restrict__ feats,     // [B, T, L]
    const float* __restrict__ transfer,  // [L, L]
    const int*   __restrict__ target,    // [B, T]
    const int*   __restrict__ startp,    // scalar (may be null -> L-2)
    const int*   __restrict__ stopp,     // scalar (may be null -> L-1)
    float*       __restrict__ out)       // [B]
{
    __shared__ __align__(16) float Psh[NB][LL];     // P broadcast (single buffer)
    __shared__ __align__(16) float part[2][LL][NB]; // per-wg partial sums
    __shared__ float v0s[NB];                       // stabilizer anchors
    __shared__ float smax[NB][4];
    __shared__ float ssum[NB][4];
    __shared__ float sg[NB][8];

    const int tid  = threadIdx.x;
    const int lane = tid & 31;
    const int wid  = tid >> 5;
    const int j    = tid & (LL - 1);
    const int wg   = tid >> 7;           // 0 or 1
    const int b0   = blockIdx.x * NB;

    const int start = startp ? *startp : (LL - 2);
    const int stop  = stopp  ? *stopp  : (LL - 1);

    // ---- E half-column for (wg, j): 32 f32x2 i-pairs ----
    unsigned long long E2[32];
    {
        const int i0 = wg << 6;
#pragma unroll
        for (int m = 0; m < 32; m++) {
            const float ea = __expf(transfer[(i0 + 2 * m)     * LL + j]);
            const float eb = __expf(transfer[(i0 + 2 * m + 1) * LL + j]);
            E2[m] = pack2(ea, eb);
        }
    }

    const float* fb[NB];
    const int*   tb[NB];
#pragma unroll
    for (int nb = 0; nb < NB; nb++) {
        fb[nb] = feats  + (size_t)(b0 + nb) * TT * LL;
        tb[nb] = target + (size_t)(b0 + nb) * TT;
    }

    // ---- Gold-path partial sums (emit + trans), strided over t, all 256 thr ----
    float g[NB];
#pragma unroll
    for (int nb = 0; nb < NB; nb++) {
        float acc = 0.f;
        for (int t = 1 + tid; t < TT; t += NTHR) {
            const int tg = tb[nb][t];
            const int pr = (t == 1) ? start : tb[nb][t - 1];
            acc += fb[nb][t * LL + tg] + transfer[pr * LL + tg];
        }
        g[nb] = acc;
    }

    // ---- Recurrence state (wg0 only) ----
    float prev[NB] = {0, 0, 0, 0};
    float fcur[NB] = {0, 0, 0, 0};
    float f1[NB]   = {0, 0, 0, 0};
    float mhat[NB] = {0, 0, 0, 0};
    if (wg == 0) {
        const float tstart = transfer[start * LL + j];
#pragma unroll
        for (int nb = 0; nb < NB; nb++) {
            prev[nb] = fb[nb][1 * LL + j] + tstart;
            fcur[nb] = fb[nb][2 * LL + j];
            f1[nb]   = fb[nb][3 * LL + j];
        }
    }

    // ---- Main scan: t = 2 .. T-1 ----
    const ulonglong2* Pu2 = reinterpret_cast<const ulonglong2*>(&Psh[0][0]);
    const int poff = wg << 4;            // 16 ulonglong2 into each batch's row

    for (int t = 2; t < TT; t++) {
        float f2[NB], v[NB];
        if (wg == 0) {
            const int tn = (t + 2 < TT) ? (t + 2) : (TT - 1);
#pragma unroll
            for (int nb = 0; nb < NB; nb++) {
                f2[nb] = fb[nb][tn * LL + j];            // prefetch 2 ahead
                v[nb]  = prev[nb] + fcur[nb];
                Psh[nb][j] = __expf(v[nb] - mhat[nb]);
            }
            if (tid == 0) {
#pragma unroll
                for (int nb = 0; nb < NB; nb++) v0s[nb] = v[nb];
            }
        }
        __syncthreads();                  // SYNC A: Psh, v0s ready

        // cache anchors right after the barrier (avoids race with next write)
        float v0r[NB];
#pragma unroll
        for (int nb = 0; nb < NB; nb++) v0r[nb] = v0s[nb];

        // partial S over own i-half: 16 LDS.128 + 32 FFMA2 per batch
        unsigned long long a0[NB], a1[NB];
#pragma unroll
        for (int nb = 0; nb < NB; nb++) { a0[nb] = 0ull; a1[nb] = 0ull; }
#pragma unroll
        for (int k = 0; k < 16; k++) {
            const unsigned long long e0 = E2[2 * k];
            const unsigned long long e1 = E2[2 * k + 1];
#pragma unroll
            for (int nb = 0; nb < NB; nb++) {
                const ulonglong2 q = Pu2[(nb << 5) + poff + k];
                a0[nb] = fma2(q.x, e0, a0[nb]);
                a1[nb] = fma2(q.y, e1, a1[nb]);
            }
        }
        float s[NB];
#pragma unroll
        for (int nb = 0; nb < NB; nb++) {
            float xl, xh;
            unpack2(xl, xh, add2(a0[nb], a1[nb]));
            s[nb] = xl + xh;
        }
        *reinterpret_cast<float4*>(&part[wg][j][0]) =
            make_float4(s[0], s[1], s[2], s[3]);
        __syncthreads();                  // SYNC B: partials ready

        if (wg == 0) {
            const float4 o = *reinterpret_cast<const float4*>(&part[1][j][0]);
            prev[0] = mhat[0] + __logf(s[0] + o.x);
            prev[1] = mhat[1] + __logf(s[1] + o.y);
            prev[2] = mhat[2] + __logf(s[2] + o.z);
            prev[3] = mhat[3] + __logf(s[3] + o.w);
#pragma unroll
            for (int nb = 0; nb < NB; nb++) {
                mhat[nb] = v0r[nb] + GROWTH;   // anchor for next step
                fcur[nb] = f1[nb];
                f1[nb]   = f2[nb];
            }
        }
    }

    // ---- Epilogue ----
    // gold-score: per-warp reduce over all 8 warps
#pragma unroll
    for (int nb = 0; nb < NB; nb++) {
        float gg = g[nb];
#pragma unroll
        for (int off = 16; off; off >>= 1)
            gg += __shfl_xor_sync(0xffffffffu, gg, off);
        if (lane == 0) sg[nb][wid] = gg;
    }

    const float tstop = transfer[j * LL + stop];
    if (wg == 0) {
#pragma unroll
        for (int nb = 0; nb < NB; nb++) {
            float m = prev[nb] + tstop;
#pragma unroll
            for (int off = 16; off; off >>= 1)
                m = fmaxf(m, __shfl_xor_sync(0xffffffffu, m, off));
            if (lane == 0) smax[nb][wid] = m;
        }
    }
    __syncthreads();

    if (wg == 0) {
#pragma unroll
        for (int nb = 0; nb < NB; nb++) {
            const float mm = fmaxf(fmaxf(smax[nb][0], smax[nb][1]),
                                   fmaxf(smax[nb][2], smax[nb][3]));
            float es = __expf((prev[nb] + tstop) - mm);
#pragma unroll
            for (int off = 16; off; off >>= 1)
                es += __shfl_xor_sync(0xffffffffu, es, off);
            if (lane == 0) ssum[nb][wid] = es;
        }
    }
    __syncthreads();

    if (tid < NB) {
        const int nb = tid;
        const float mm = fmaxf(fmaxf(smax[nb][0], smax[nb][1]),
                               fmaxf(smax[nb][2], smax[nb][3]));
        const float Ssum = ssum[nb][0] + ssum[nb][1] + ssum[nb][2] + ssum[nb][3];
        const float sentence = mm + __logf(Ssum);
        float gsum = 0.f;
#pragma unroll
        for (int w = 0; w < 8; w++) gsum += sg[nb][w];
        const float emit0 = fb[nb][start];  // feats[b, 0, start]
        out[b0 + nb] = sentence - __expf(emit0 + gsum);
    }
}

extern "C" void kernel_launch(void* const* d_in, const int* in_sizes, int n_in,
                              void* d_out, int out_size) {
    const float* feats    = (const float*)d_in[0];
    const float* transfer = (const float*)d_in[1];
    const int*   target   = (const int*)d_in[2];
    const int*   startp   = (n_in >= 4) ? (const int*)d_in[3] : nullptr;
    const int*   stopp    = (n_in >= 5) ? (const int*)d_in[4] : nullptr;

    crf_kernel<<<NCTA, NTHR>>>(feats, transfer, target, startp, stopp, (float*)d_out);
}

// round 6
// speedup vs baseline: 1.1960x; 1.1960x over previous
#include <cuda_runtime.h>

// Problem constants (fixed by the dataset): B=512, T=512, L=128
#define BB 512
#define TT 512
#define LL 128
#define NB 2                 // batches per CTA
#define NCTA (BB / NB)       // 256 CTAs, 2 co-resident per SM -> one wave
#define GROWTH 4.8520303f    // ln(128): expected per-step growth of log-partition

__device__ __forceinline__ unsigned long long pack2(float x, float y) {
    unsigned long long r;
    asm("mov.b64 %0, {%1, %2};" : "=l"(r) : "f"(x), "f"(y));
    return r;
}
__device__ __forceinline__ void unpack2(float& x, float& y, unsigned long long v) {
    asm("mov.b64 {%0, %1}, %2;" : "=f"(x), "=f"(y) : "l"(v));
}
// Packed f32x2 FMA — 2x fp32 throughput on sm_103a.
__device__ __forceinline__ unsigned long long fma2(unsigned long long a,
                                                   unsigned long long b,
                                                   unsigned long long c) {
    unsigned long long d;
    asm("fma.rn.f32x2 %0, %1, %2, %3;" : "=l"(d) : "l"(a), "l"(b), "l"(c));
    return d;
}
__device__ __forceinline__ unsigned long long add2(unsigned long long a,
                                                   unsigned long long b) {
    unsigned long long d;
    asm("add.rn.f32x2 %0, %1, %2;" : "=l"(d) : "l"(a), "l"(b));
    return d;
}

// Persistent: one CTA = NB=2 batches for the whole scan; TWO independent CTAs
// per SM so one CTA's FMA/LDS stream fills the other's barrier-convoy and
// serial log/exp bubbles. 128 threads; thread tid owns output label j = tid.
// E column j (exp(transfer[:, j])) lives in registers as 64 f32x2 i-pairs,
// shared by both batches' dot products. One __syncthreads per step
// (double-buffered P broadcast), self-anchoring stabilizer (no max reduce).
__global__ __launch_bounds__(128, 2) void crf_kernel(
    const float* __restrict__ feats,     // [B, T, L]
    const float* __restrict__ transfer,  // [L, L]
    const int*   __restrict__ target,    // [B, T]
    const int*   __restrict__ startp,    // scalar (may be null -> L-2)
    const int*   __restrict__ stopp,     // scalar (may be null -> L-1)
    float*       __restrict__ out)       // [B]
{
    __shared__ __align__(16) float Psh[2][NB][LL];  // double-buffered P per batch
    __shared__ float v0s[2][NB];         // stabilizer anchors
    __shared__ float smax[NB][4];
    __shared__ float ssum[NB][4];
    __shared__ float sg[NB][4];

    const int tid  = threadIdx.x;
    const int lane = tid & 31;
    const int wid  = tid >> 5;
    const int b0   = blockIdx.x * NB;

    const int start = startp ? *startp : (LL - 2);
    const int stop  = stopp  ? *stopp  : (LL - 1);

    // ---- E column for j = tid: E2[m] = (exp(T[2m,j]), exp(T[2m+1,j])) ----
    unsigned long long E2[LL / 2];
#pragma unroll
    for (int m = 0; m < LL / 2; m++) {
        const float ea = __expf(transfer[(2 * m)     * LL + tid]);  // coalesced
        const float eb = __expf(transfer[(2 * m + 1) * LL + tid]);
        E2[m] = pack2(ea, eb);
    }

    const float* fb[NB];
    const int*   tb[NB];
#pragma unroll
    for (int nb = 0; nb < NB; nb++) {
        fb[nb] = feats  + (size_t)(b0 + nb) * TT * LL;
        tb[nb] = target + (size_t)(b0 + nb) * TT;
    }

    // ---- Gold-path partial sums (emit + trans), strided over t ----
    float g[NB];
#pragma unroll
    for (int nb = 0; nb < NB; nb++) {
        float acc = 0.f;
        for (int t = 1 + tid; t < TT; t += 128) {
            const int tg = tb[nb][t];
            const int pr = (t == 1) ? start : tb[nb][t - 1];
            acc += fb[nb][t * LL + tg] + transfer[pr * LL + tg];
        }
        g[nb] = acc;
    }

    // ---- prev0 = feats[:,1,:] + transfer[start,:] ----
    float prev[NB], fcur[NB], f1[NB], mhat[NB];
    const float tstart = transfer[start * LL + tid];
#pragma unroll
    for (int nb = 0; nb < NB; nb++) {
        prev[nb] = fb[nb][1 * LL + tid] + tstart;
        fcur[nb] = fb[nb][2 * LL + tid];
        f1[nb]   = fb[nb][3 * LL + tid];
        mhat[nb] = 0.f;
    }

    // ---- Main scan: t = 2 .. T-1 ----
    for (int t = 2; t < TT; t++) {
        const int tn = (t + 2 < TT) ? (t + 2) : (TT - 1);
        float f2[NB];
        float v[NB];
        const int buf = t & 1;
#pragma unroll
        for (int nb = 0; nb < NB; nb++) {
            f2[nb] = fb[nb][tn * LL + tid];            // prefetch, 2 steps ahead
            v[nb]  = prev[nb] + fcur[nb];
            Psh[buf][nb][tid] = __expf(v[nb] - mhat[nb]);
        }
        if (tid == 0) {
#pragma unroll
            for (int nb = 0; nb < NB; nb++) v0s[buf][nb] = v[nb];
        }
        __syncthreads();

        // S_j[nb] = sum_i P[nb][i] * E[i, j]; LDS.128 broadcast -> FFMA2.
        const ulonglong2* P0 = reinterpret_cast<const ulonglong2*>(Psh[buf][0]);
        const ulonglong2* P1 = reinterpret_cast<const ulonglong2*>(Psh[buf][1]);
        unsigned long long a0 = 0ull, b0a = 0ull;
        unsigned long long a1 = 0ull, b1a = 0ull;
#pragma unroll
        for (int k = 0; k < LL / 4; k++) {
            const unsigned long long e0 = E2[2 * k];
            const unsigned long long e1 = E2[2 * k + 1];
            const ulonglong2 q0 = P0[k];
            a0  = fma2(q0.x, e0, a0);
            b0a = fma2(q0.y, e1, b0a);
            const ulonglong2 q1 = P1[k];
            a1  = fma2(q1.x, e0, a1);
            b1a = fma2(q1.y, e1, b1a);
        }
        a0 = add2(a0, b0a);
        a1 = add2(a1, b1a);

        float xl, xh;
        unpack2(xl, xh, a0);
        prev[0] = mhat[0] + __logf(xl + xh);
        unpack2(xl, xh, a1);
        prev[1] = mhat[1] + __logf(xl + xh);

#pragma unroll
        for (int nb = 0; nb < NB; nb++) {
            mhat[nb] = v0s[buf][nb] + GROWTH;   // anchor for next step
            fcur[nb] = f1[nb];
            f1[nb]   = f2[nb];
        }
    }

    // ---- Epilogue: sentence scores and gold scores ----
    const float tstop = transfer[tid * LL + stop];
#pragma unroll
    for (int nb = 0; nb < NB; nb++) {
        const float vv = prev[nb] + tstop;
        float m = vv;
#pragma unroll
        for (int off = 16; off; off >>= 1)
            m = fmaxf(m, __shfl_xor_sync(0xffffffffu, m, off));
        if (lane == 0) smax[nb][wid] = m;
    }
    __syncthreads();
#pragma unroll
    for (int nb = 0; nb < NB; nb++) {
        const float mm = fmaxf(fmaxf(smax[nb][0], smax[nb][1]),
                               fmaxf(smax[nb][2], smax[nb][3]));
        float es = __expf((prev[nb] + tstop) - mm);
        float gg = g[nb];
#pragma unroll
        for (int off = 16; off; off >>= 1) {
            es += __shfl_xor_sync(0xffffffffu, es, off);
            gg += __shfl_xor_sync(0xffffffffu, gg, off);
        }
        if (lane == 0) { ssum[nb][wid] = es; sg[nb][wid] = gg; }
    }
    __syncthreads();

    if (tid < NB) {
        const int nb = tid;
        const float mm = fmaxf(fmaxf(smax[nb][0], smax[nb][1]),
                               fmaxf(smax[nb][2], smax[nb][3]));
        const float Ssum = ssum[nb][0] + ssum[nb][1] + ssum[nb][2] + ssum[nb][3];
        const float sentence = mm + __logf(Ssum);
        const float gsum = sg[nb][0] + sg[nb][1] + sg[nb][2] + sg[nb][3];
        const float emit0 = fb[nb][start];  // feats[b, 0, start]
        out[b0 + nb] = sentence - __expf(emit0 + gsum);
    }
}

extern "C" void kernel_launch(void* const* d_in, const int* in_sizes, int n_in,
                              void* d_out, int out_size) {
    const float* feats    = (const float*)d_in[0];
    const float* transfer = (const float*)d_in[1];
    const int*   target   = (const int*)d_in[2];
    const int*   startp   = (n_in >= 4) ? (const int*)d_in[3] : nullptr;
    const int*   stopp    = (n_in >= 5) ? (const int*)d_in[4] : nullptr;

    crf_kernel<<<NCTA, 128>>>(feats, transfer, target, startp, stopp, (float*)d_out);
}

// round 7
// speedup vs baseline: 1.2727x; 1.0641x over previous
#include <cuda_runtime.h>

// Problem constants (fixed by the dataset): B=512, T=512, L=128
#define BB 512
#define TT 512
#define LL 128
#define NB 2                 // batches per CTA
#define NCTA (BB / NB)       // 256 CTAs, 2 co-resident per SM
#define PROW 136             // padded P row (floats): cols 0-63 at [0,64), 64-127 at [68,132)
#define PROW_U2 (PROW / 4)   // 34 ulonglong2 per row
#define GROWTH 4.8520303f    // ln(128): expected per-step growth of log-partition

__device__ __forceinline__ unsigned long long pack2(float x, float y) {
    unsigned long long r;
    asm("mov.b64 %0, {%1, %2};" : "=l"(r) : "f"(x), "f"(y));
    return r;
}
__device__ __forceinline__ void unpack2(float& x, float& y, unsigned long long v) {
    asm("mov.b64 {%0, %1}, %2;" : "=f"(x), "=f"(y) : "l"(v));
}
// Packed f32x2 FMA — 2x fp32 throughput on sm_103a.
__device__ __forceinline__ unsigned long long fma2(unsigned long long a,
                                                   unsigned long long b,
                                                   unsigned long long c) {
    unsigned long long d;
    asm("fma.rn.f32x2 %0, %1, %2, %3;" : "=l"(d) : "l"(a), "l"(b), "l"(c));
    return d;
}
__device__ __forceinline__ unsigned long long add2(unsigned long long a,
                                                   unsigned long long b) {
    unsigned long long d;
    asm("add.rn.f32x2 %0, %1, %2;" : "=l"(d) : "l"(a), "l"(b));
    return d;
}
__device__ __forceinline__ float hsum2(unsigned long long v) {
    float x, y;
    unpack2(x, y, v);
    return x + y;
}

// Persistent: one CTA = NB=2 batches, 2 CTAs/SM (independent barrier domains).
// 128 threads. Thread (warp w, lane l):
//   jj  = w*16 + (l & 15)            : base column index in [0,64)
//   ih  = l >> 4                     : i-half  [64*ih, 64*ih+64)
//   owns TWO j-columns: j0 = jj, j1 = jj + 64 (E regs: 2 x 32 f32x2)
//   computes partial dots over its i-half; halves combine via shfl_xor(16);
//   thread's OWN recurrence column is (ih ? j1 : j0)  -> all 128 cols covered.
// Each LDS.128 (half-warp broadcast, pad-deconflicted) feeds 4 FFMA2:
// LDS instruction stream halved vs the j-ownership layout.
__global__ __launch_bounds__(128, 2) void crf_kernel(
    const float* __restrict__ feats,     // [B, T, L]
    const float* __restrict__ transfer,  // [L, L]
    const int*   __restrict__ target,    // [B, T]
    const int*   __restrict__ startp,    // scalar (may be null -> L-2)
    const int*   __restrict__ stopp,     // scalar (may be null -> L-1)
    float*       __restrict__ out)       // [B]
{
    __shared__ __align__(16) float Psh[2][NB][PROW];  // double-buffered padded P
    __shared__ float v0s[2][NB];         // stabilizer anchors
    __shared__ float smax[NB][4];
    __shared__ float ssum[NB][4];
    __shared__ float sg[NB][4];

    const int tid  = threadIdx.x;
    const int lane = tid & 31;
    const int wid  = tid >> 5;
    const int jj   = (wid << 4) + (lane & 15);
    const int ih   = lane >> 4;                 // i-half
    const int jown = jj + (ih << 6);            // recurrence column owned
    const int fown = jj + ih * 68;              // padded float offset of jown
    const int b0   = blockIdx.x * NB;

    const int start = startp ? *startp : (LL - 2);
    const int stop  = stopp  ? *stopp  : (LL - 1);

    // ---- E tiles: i in [64*ih, 64*ih+64) for columns j0=jj and j1=jj+64 ----
    unsigned long long Ea[32], Eb[32];   // Ea: column jj, Eb: column jj+64
    {
        const int i0 = ih << 6;
#pragma unroll
        for (int m = 0; m < 32; m++) {
            const int ia = i0 + 2 * m;
            Ea[m] = pack2(__expf(transfer[ia * LL + jj]),
                          __expf(transfer[(ia + 1) * LL + jj]));
            Eb[m] = pack2(__expf(transfer[ia * LL + jj + 64]),
                          __expf(transfer[(ia + 1) * LL + jj + 64]));
        }
    }

    const float* fb[NB];
    const int*   tb[NB];
#pragma unroll
    for (int nb = 0; nb < NB; nb++) {
        fb[nb] = feats  + (size_t)(b0 + nb) * TT * LL;
        tb[nb] = target + (size_t)(b0 + nb) * TT;
    }

    // ---- Gold-path partial sums (emit + trans), strided over t ----
    float g[NB];
#pragma unroll
    for (int nb = 0; nb < NB; nb++) {
        float acc = 0.f;
        for (int t = 1 + tid; t < TT; t += 128) {
            const int tg = tb[nb][t];
            const int pr = (t == 1) ? start : tb[nb][t - 1];
            acc += fb[nb][t * LL + tg] + transfer[pr * LL + tg];
        }
        g[nb] = acc;
    }

    // ---- Recurrence state for the owned column ----
    float prev[NB], fcur[NB], f1[NB], mhat[NB];
    const float tstart = transfer[start * LL + jown];
#pragma unroll
    for (int nb = 0; nb < NB; nb++) {
        prev[nb] = fb[nb][1 * LL + jown] + tstart;
        fcur[nb] = fb[nb][2 * LL + jown];
        f1[nb]   = fb[nb][3 * LL + jown];
        mhat[nb] = 0.f;
    }

    // LDS base (in ulonglong2) of this thread's i-half within a P row:
    // ih=0 -> u2 index 0..15 (floats 0..63), ih=1 -> u2 index 17..32 (floats 68..131)
    const int pbase = ih * 17;

    // ---- Main scan: t = 2 .. T-1 ----
    for (int t = 2; t < TT; t++) {
        const int tn = (t + 2 < TT) ? (t + 2) : (TT - 1);
        float f2[NB], v[NB];
        const int buf = t & 1;
#pragma unroll
        for (int nb = 0; nb < NB; nb++) {
            f2[nb] = fb[nb][tn * LL + jown];           // prefetch, 2 steps ahead
            v[nb]  = prev[nb] + fcur[nb];
            Psh[buf][nb][fown] = __expf(v[nb] - mhat[nb]);
        }
        if (tid == 0) {                                // tid 0 owns column 0
#pragma unroll
            for (int nb = 0; nb < NB; nb++) v0s[buf][nb] = v[nb];
        }
        __syncthreads();

        // Partial dots over own i-half for both columns, both batches.
        const ulonglong2* P0 =
            reinterpret_cast<const ulonglong2*>(Psh[buf][0]) + pbase;
        const ulonglong2* P1 =
            reinterpret_cast<const ulonglong2*>(Psh[buf][1]) + pbase;
        unsigned long long aA0 = 0ull, bA0 = 0ull, aB0 = 0ull, bB0 = 0ull;
        unsigned long long aA1 = 0ull, bA1 = 0ull, aB1 = 0ull, bB1 = 0ull;
#pragma unroll
        for (int k = 0; k < 16; k++) {
            const unsigned long long ea0 = Ea[2 * k];
            const unsigned long long ea1 = Ea[2 * k + 1];
            const unsigned long long eb0 = Eb[2 * k];
            const unsigned long long eb1 = Eb[2 * k + 1];
            const ulonglong2 q0 = P0[k];
            aA0 = fma2(q0.x, ea0, aA0);
            bA0 = fma2(q0.y, ea1, bA0);
            aB0 = fma2(q0.x, eb0, aB0);
            bB0 = fma2(q0.y, eb1, bB0);
            const ulonglong2 q1 = P1[k];
            aA1 = fma2(q1.x, ea0, aA1);
            bA1 = fma2(q1.y, ea1, bA1);
            aB1 = fma2(q1.x, eb0, aB1);
            bB1 = fma2(q1.y, eb1, bB1);
        }
        // column A (jj) and column B (jj+64) sums over own i-half
        float sA0 = hsum2(add2(aA0, bA0));
        float sB0 = hsum2(add2(aB0, bB0));
        float sA1 = hsum2(add2(aA1, bA1));
        float sB1 = hsum2(add2(aB1, bB1));
        // combine i-halves within the warp (lane l <-> l^16 holds the other half)
        sA0 += __shfl_xor_sync(0xffffffffu, sA0, 16);
        sB0 += __shfl_xor_sync(0xffffffffu, sB0, 16);
        sA1 += __shfl_xor_sync(0xffffffffu, sA1, 16);
        sB1 += __shfl_xor_sync(0xffffffffu, sB1, 16);

        const float s0 = ih ? sB0 : sA0;   // full dot for owned column, batch 0
        const float s1 = ih ? sB1 : sA1;   // batch 1

        prev[0] = mhat[0] + __logf(s0);
        prev[1] = mhat[1] + __logf(s1);
#pragma unroll
        for (int nb = 0; nb < NB; nb++) {
            mhat[nb] = v0s[buf][nb] + GROWTH;  // anchor for next step
            fcur[nb] = f1[nb];
            f1[nb]   = f2[nb];
        }
    }

    // ---- Epilogue: sentence scores and gold scores ----
    const float tstop = transfer[jown * LL + stop];
#pragma unroll
    for (int nb = 0; nb < NB; nb++) {
        const float vv = prev[nb] + tstop;
        float m = vv;
#pragma unroll
        for (int off = 16; off; off >>= 1)
            m = fmaxf(m, __shfl_xor_sync(0xffffffffu, m, off));
        if (lane == 0) smax[nb][wid] = m;
    }
    __syncthreads();
#pragma unroll
    for (int nb = 0; nb < NB; nb++) {
        const float mm = fmaxf(fmaxf(smax[nb][0], smax[nb][1]),
                               fmaxf(smax[nb][2], smax[nb][3]));
        float es = __expf((prev[nb] + tstop) - mm);
        float gg = g[nb];
#pragma unroll
        for (int off = 16; off; off >>= 1) {
            es += __shfl_xor_sync(0xffffffffu, es, off);
            gg += __shfl_xor_sync(0xffffffffu, gg, off);
        }
        if (lane == 0) { ssum[nb][wid] = es; sg[nb][wid] = gg; }
    }
    __syncthreads();

    if (tid < NB) {
        const int nb = tid;
        const float mm = fmaxf(fmaxf(smax[nb][0], smax[nb][1]),
                               fmaxf(smax[nb][2], smax[nb][3]));
        const float Ssum = ssum[nb][0] + ssum[nb][1] + ssum[nb][2] + ssum[nb][3];
        const float sentence = mm + __logf(Ssum);
        const float gsum = sg[nb][0] + sg[nb][1] + sg[nb][2] + sg[nb][3];
        const float emit0 = fb[nb][start];  // feats[b, 0, start]
        out[b0 + nb] = sentence - __expf(emit0 + gsum);
    }
}

extern "C" void kernel_launch(void* const* d_in, const int* in_sizes, int n_in,
                              void* d_out, int out_size) {
    const float* feats    = (const float*)d_in[0];
    const float* transfer = (const float*)d_in[1];
    const int*   target   = (const int*)d_in[2];
    const int*   startp   = (n_in >= 4) ? (const int*)d_in[3] : nullptr;
    const int*   stopp    = (n_in >= 5) ? (const int*)d_in[4] : nullptr;

    crf_kernel<<<NCTA, 128>>>(feats, transfer, target, startp, stopp, (float*)d_out);
}